// round 9
// baseline (speedup 1.0000x reference)
#include <cuda_runtime.h>

#define Bn 256
#define Sn 196
#define Dn 2048
#define Hn 512
#define KSPLIT 32
#define KCHUNK (Dn / KSPLIT)   // 64
#define BK 16
#define TM 128
#define TN 64
#define ASTR 132   // 128 + 4, 16B-aligned row stride
#define BSTR 68    // 64 + 4

// Scratch (no cudaMalloc allowed)
__device__ __align__(16) float g_atth_part[KSPLIT * Bn * Hn];  // 16 MB partials
__device__ __align__(16) float g_atth[Bn * Hn];
__device__ float g_scores[Bn * Sn];

// Hardware tanh approximation (MUFU.TANH, 1 instr; validated rel_err 2.6e-6)
__device__ __forceinline__ float htanh(float x) {
    float y;
    asm("tanh.approx.f32 %0, %1;" : "=f"(y) : "f"(x));
    return y;
}

// ---------------------------------------------------------------------------
// Kernel 1: split-K GEMM partials, 128m x 64n tile, 8m x 4n per thread.
//   part[z][m][n] = sum_{k in chunk z} h[m,k] * W[n,k]
// LDS economics: 3 x LDS.128 (48B) per 32 FMA = 1.5 B/FMA (was 2.0) ->
// smem-crossbar floor drops from ~15us to ~12us. Double-buffered stages,
// one __syncthreads per BK-tile. Grid (8, 2, 32) = 512 blocks.
// ---------------------------------------------------------------------------
__global__ __launch_bounds__(256) void k_h2att_sk(const float* __restrict__ A,
                                                  const float* __restrict__ W) {
    __shared__ __align__(16) float As[2][BK * ASTR];   // [stage][k][m]
    __shared__ __align__(16) float Bs[2][BK * BSTR];   // [stage][k][n]
    const int tid = threadIdx.x;
    const int tx = tid & 15;          // n-quad -> n = tx*4
    const int ty = tid >> 4;          // m-oct  -> m = ty*8
    const int n0 = blockIdx.x * TN;
    const int m0 = blockIdx.y * TM;
    const int kbase = blockIdx.z * KCHUNK;

    const int fr = tid >> 2;          // 0..63 (fill row)
    const int fc = (tid & 3) * 4;     // 0,4,8,12 (fill k-offset)

    const float* aptr0 = &A[(m0 + fr) * Dn + kbase + fc];        // rows 0..63
    const float* aptr1 = &A[(m0 + fr + 64) * Dn + kbase + fc];   // rows 64..127
    const float* bptr  = &W[(n0 + fr) * Dn + kbase + fc];

    float acc[8][4] = {};

    // prologue: tile 0 -> stage 0
    {
        float4 a0 = *(const float4*)aptr0;
        float4 a1 = *(const float4*)aptr1;
        float4 b4 = *(const float4*)bptr;
#pragma unroll
        for (int i = 0; i < 4; i++) {
            As[0][(fc + i) * ASTR + fr]      = (&a0.x)[i];
            As[0][(fc + i) * ASTR + fr + 64] = (&a1.x)[i];
            Bs[0][(fc + i) * BSTR + fr]      = (&b4.x)[i];
        }
    }
    __syncthreads();

    int buf = 0;
#pragma unroll
    for (int kt = 0; kt < KCHUNK; kt += BK) {
        const bool has_next = (kt + BK) < KCHUNK;
        float4 a0, a1, b4;
        if (has_next) {                    // LDG in flight through compute
            a0 = *(const float4*)(aptr0 + kt + BK);
            a1 = *(const float4*)(aptr1 + kt + BK);
            b4 = *(const float4*)(bptr + kt + BK);
        }

#pragma unroll
        for (int k = 0; k < BK; k++) {
            float4 alo = *(const float4*)&As[buf][k * ASTR + ty * 8];
            float4 ahi = *(const float4*)&As[buf][k * ASTR + ty * 8 + 4];
            float4 b = *(const float4*)&Bs[buf][k * BSTR + tx * 4];
            acc[0][0] += alo.x * b.x; acc[0][1] += alo.x * b.y;
            acc[0][2] += alo.x * b.z; acc[0][3] += alo.x * b.w;
            acc[1][0] += alo.y * b.x; acc[1][1] += alo.y * b.y;
            acc[1][2] += alo.y * b.z; acc[1][3] += alo.y * b.w;
            acc[2][0] += alo.z * b.x; acc[2][1] += alo.z * b.y;
            acc[2][2] += alo.z * b.z; acc[2][3] += alo.z * b.w;
            acc[3][0] += alo.w * b.x; acc[3][1] += alo.w * b.y;
            acc[3][2] += alo.w * b.z; acc[3][3] += alo.w * b.w;
            acc[4][0] += ahi.x * b.x; acc[4][1] += ahi.x * b.y;
            acc[4][2] += ahi.x * b.z; acc[4][3] += ahi.x * b.w;
            acc[5][0] += ahi.y * b.x; acc[5][1] += ahi.y * b.y;
            acc[5][2] += ahi.y * b.z; acc[5][3] += ahi.y * b.w;
            acc[6][0] += ahi.z * b.x; acc[6][1] += ahi.z * b.y;
            acc[6][2] += ahi.z * b.z; acc[6][3] += ahi.z * b.w;
            acc[7][0] += ahi.w * b.x; acc[7][1] += ahi.w * b.y;
            acc[7][2] += ahi.w * b.z; acc[7][3] += ahi.w * b.w;
        }

        if (has_next) {
            const int nb = buf ^ 1;
#pragma unroll
            for (int i = 0; i < 4; i++) {
                As[nb][(fc + i) * ASTR + fr]      = (&a0.x)[i];
                As[nb][(fc + i) * ASTR + fr + 64] = (&a1.x)[i];
                Bs[nb][(fc + i) * BSTR + fr]      = (&b4.x)[i];
            }
            __syncthreads();
            buf = nb;
        }
    }

    float* dst = g_atth_part + (size_t)blockIdx.z * (Bn * Hn);
#pragma unroll
    for (int i = 0; i < 8; i++) {
        float4 v = make_float4(acc[i][0], acc[i][1], acc[i][2], acc[i][3]);
        *(float4*)&dst[(m0 + ty * 8 + i) * Hn + n0 + tx * 4] = v;
    }
}

// ---------------------------------------------------------------------------
// Kernel 2: reduce the 32 split-K partials + bias -> g_atth[B*H].
// 131072 elements, 16 MB L2-resident reads. Grid 512 x 256.
// ---------------------------------------------------------------------------
__global__ __launch_bounds__(256) void k_reduce(const float* __restrict__ bias) {
    const int idx = blockIdx.x * 256 + threadIdx.x;   // b*Hn + h
    float acc = bias[idx & (Hn - 1)];
#pragma unroll
    for (int z = 0; z < KSPLIT; z++)
        acc += g_atth_part[z * (Bn * Hn) + idx];
    g_atth[idx] = acc;
}

// ---------------------------------------------------------------------------
// Kernel 3: raw scores, 2-slot ILP + hardware tanh. Grid (B, 7), 448 threads.
//   scores[b,s] = sum_h tanh(p[b,s,h] + att_h[b,h]) * w_alpha[h] + b_alpha
// ---------------------------------------------------------------------------
__global__ __launch_bounds__(448) void k_scores(const float* __restrict__ p_att,
                                                const float* __restrict__ w_alpha,
                                                const float* __restrict__ b_alpha) {
    __shared__ float ah[Hn];
    __shared__ float wa[Hn];

    const int b = blockIdx.x;
    const int sgrp = blockIdx.y;          // 0..6, 28 slots each
    const int tid = threadIdx.x;
    const int lane = tid & 31;
    const int warp = tid >> 5;            // 0..13

    for (int h = tid; h < Hn; h += 448) {
        ah[h] = g_atth[b * Hn + h];
        wa[h] = w_alpha[h];
    }
    __syncthreads();

    const float balpha = b_alpha[0];
    const float4* a4p = (const float4*)ah;
    const float4* w4p = (const float4*)wa;

    const int s0 = sgrp * 28 + warp * 2;
    const float4* pr0 = (const float4*)(p_att + ((long)b * Sn + s0) * Hn);
    const float4* pr1 = (const float4*)(p_att + ((long)b * Sn + s0 + 1) * Hn);

    float l0 = 0.0f, l1 = 0.0f;
#pragma unroll
    for (int i = 0; i < 4; i++) {
        const int h4 = i * 32 + lane;
        float4 pa = pr0[h4];
        float4 pb = pr1[h4];
        float4 a4 = a4p[h4];
        float4 w4 = w4p[h4];
        l0 += htanh(pa.x + a4.x) * w4.x;
        l1 += htanh(pb.x + a4.x) * w4.x;
        l0 += htanh(pa.y + a4.y) * w4.y;
        l1 += htanh(pb.y + a4.y) * w4.y;
        l0 += htanh(pa.z + a4.z) * w4.z;
        l1 += htanh(pb.z + a4.z) * w4.z;
        l0 += htanh(pa.w + a4.w) * w4.w;
        l1 += htanh(pb.w + a4.w) * w4.w;
    }
#pragma unroll
    for (int o = 16; o > 0; o >>= 1) {
        l0 += __shfl_xor_sync(0xffffffffu, l0, o);
        l1 += __shfl_xor_sync(0xffffffffu, l1, o);
    }
    if (lane == 0) {
        g_scores[b * Sn + s0]     = l0 + balpha;
        g_scores[b * Sn + s0 + 1] = l1 + balpha;
    }
}

// ---------------------------------------------------------------------------
// Kernel 4: fused masked-softmax prologue + weighted sum.
// Grid (4, B) x 128 threads. w_i = e_i*m_i / sum_j(e_j*m_j).
// ---------------------------------------------------------------------------
__global__ __launch_bounds__(128) void k_attres(const float* __restrict__ att_feats,
                                                const float* __restrict__ mask,
                                                float* __restrict__ out) {
    __shared__ float w[Sn];
    __shared__ float redm[4];
    __shared__ float reds[4];

    const int b = blockIdx.y;
    const int tid = threadIdx.x;
    const int lane = tid & 31;
    const int warp = tid >> 5;

    const float v0 = g_scores[b * Sn + tid];
    const float v1 = (tid + 128 < Sn) ? g_scores[b * Sn + tid + 128] : -3.402823e38f;

    float m = fmaxf(v0, v1);
#pragma unroll
    for (int o = 16; o > 0; o >>= 1)
        m = fmaxf(m, __shfl_xor_sync(0xffffffffu, m, o));
    if (lane == 0) redm[warp] = m;
    __syncthreads();
    m = fmaxf(fmaxf(redm[0], redm[1]), fmaxf(redm[2], redm[3]));

    float e0 = __expf(v0 - m) * mask[b * Sn + tid];
    float e1 = (tid + 128 < Sn) ? __expf(v1 - m) * mask[b * Sn + tid + 128] : 0.0f;
    float s = e0 + e1;
#pragma unroll
    for (int o = 16; o > 0; o >>= 1)
        s += __shfl_xor_sync(0xffffffffu, s, o);
    if (lane == 0) reds[warp] = s;
    __syncthreads();
    const float inv = 1.0f / (reds[0] + reds[1] + reds[2] + reds[3]);

    w[tid] = e0 * inv;
    if (tid + 128 < Sn) w[tid + 128] = e1 * inv;
    __syncthreads();

    const int d0 = blockIdx.x * 512 + tid * 4;
    const float* base = att_feats + (long)b * Sn * Dn + d0;

    float4 acc = make_float4(0.f, 0.f, 0.f, 0.f);
#pragma unroll 8
    for (int s2 = 0; s2 < Sn; s2++) {
        float4 f = *(const float4*)(base + (long)s2 * Dn);
        float ws = w[s2];
        acc.x += ws * f.x;
        acc.y += ws * f.y;
        acc.z += ws * f.z;
        acc.w += ws * f.w;
    }
    *(float4*)(out + (long)b * Dn + d0) = acc;
}

// ---------------------------------------------------------------------------

extern "C" void kernel_launch(void* const* d_in, const int* in_sizes, int n_in,
                              void* d_out, int out_size) {
    const float* h         = (const float*)d_in[0];  // [B, D]
    const float* att_feats = (const float*)d_in[1];  // [B, S, D]
    const float* p_att     = (const float*)d_in[2];  // [B, S, H]
    const float* mask      = (const float*)d_in[3];  // [B, S]
    const float* W_h2att   = (const float*)d_in[4];  // [H, D]
    const float* b_h2att   = (const float*)d_in[5];  // [H]
    const float* w_alpha   = (const float*)d_in[6];  // [H]
    const float* b_alpha   = (const float*)d_in[7];  // scalar
    float* out = (float*)d_out;                      // [B, D]

    (void)in_sizes; (void)n_in; (void)out_size;

    dim3 g1(Hn / TN, Bn / TM, KSPLIT);  // (8, 2, 32) = 512 blocks
    k_h2att_sk<<<g1, 256>>>(h, W_h2att);

    k_reduce<<<(Bn * Hn) / 256, 256>>>(b_h2att);

    dim3 g2(Bn, 7);                     // 1792 blocks, 448 thr
    k_scores<<<g2, 448>>>(p_att, w_alpha, b_alpha);

    dim3 g3(4, Bn);                     // 1024 blocks
    k_attres<<<g3, 128>>>(att_feats, mask, out);
}